// round 7
// baseline (speedup 1.0000x reference)
#include <cuda_runtime.h>
#include <math.h>

#define BB 4
#define CIN 64
#define LL 16384
#define DD 128
#define DBL 20
#define NS 8
#define NCH 256
#define CHL 64
#define LOG2E 1.4426950408889634f

__device__ float g_xin [BB*LL*DD];   // (b,l,d) pre-conv xin
__device__ float g_zg  [BB*LL*DD];   // gelu(z), (b,l,d)
__device__ float g_xs  [BB*LL*DD];   // gelu(conv(xin)), (b,l,d)
__device__ float g_xdbl[BB*DBL*LL];  // (b,c,l) pre-1dconv
__device__ float g_delta[BB*LL*DD];  // (b,l,d)
__device__ float g_Bn  [BB*LL*NS];   // (b,l,n)
__device__ float g_Cn  [BB*LL*NS];   // (b,l,n)
__device__ float g_ap  [BB*NCH*DD*NS];
__device__ float g_hs  [BB*NCH*DD*NS];
__device__ float g_hi  [BB*NCH*DD*NS];
__device__ float g_Ascl[DD*NS];      // -exp(A_logs)*log2e
__device__ int   g_afast;            // 1 if A[d][n] == (n+1)*A[d][0]

__device__ __forceinline__ float gelu_exact(float x){
    return 0.5f*x*(1.f + erff(x*0.70710678118654752f));
}
__device__ __forceinline__ float ex2(float x){
    float r; asm("ex2.approx.f32 %0, %1;" : "=f"(r) : "f"(x)); return r;
}
__device__ __forceinline__ float softplus_fast(float x){
    float e = __expf(-fabsf(x));
    return fmaxf(x, 0.f) + __logf(1.f + e);
}
// packed fp32x2 helpers
__device__ __forceinline__ unsigned long long pk2(float a, float b){
    unsigned long long r; asm("mov.b64 %0, {%1, %2};" : "=l"(r) : "f"(a), "f"(b)); return r;
}
__device__ __forceinline__ void fma2(unsigned long long &d, unsigned long long a, unsigned long long b){
    asm("fma.rn.f32x2 %0, %1, %2, %0;" : "+l"(d) : "l"(a), "l"(b));
}
__device__ __forceinline__ float2 up2(unsigned long long v){
    float2 f; asm("mov.b64 {%0, %1}, %2;" : "=f"(f.x), "=f"(f.y) : "l"(v)); return f;
}

// ------------------------------------------- K0: precompute A scales + structure flag
__global__ void k0_prep(const float* __restrict__ A_logs){
    __shared__ int ok_sh;
    int tid = threadIdx.x;   // 128 = d
    if (tid == 0) ok_sh = 1;
    __syncthreads();
    float a[NS];
#pragma unroll
    for (int n = 0; n < NS; n++){
        a[n] = -__expf(A_logs[tid*NS+n]) * LOG2E;
        g_Ascl[tid*NS+n] = a[n];
    }
    bool ok = true;
#pragma unroll
    for (int n = 1; n < NS; n++)
        ok &= fabsf(a[n] - (n+1)*a[0]) <= 1e-5f * fabsf(a[n]);
    if (!ok) atomicAnd(&ok_sh, 0);
    __syncthreads();
    if (tid == 0) g_afast = ok_sh;
}

// ---------------------------------------------------------------- K1: in_proj
__global__ void k1_inproj(const float* __restrict__ x, const float* __restrict__ Wp){
    __shared__ float xsm[64][68];   // [c][l]
    __shared__ float wsm[64][68];   // [c][d_local]
    int tid = threadIdx.x;
    int lt = blockIdx.x >> 2;
    int dt = blockIdx.x & 3;
    int b  = lt >> 8;
    int l0 = (lt & 255) << 6;
    int d0 = dt << 6;
    for (int i = tid; i < 1024; i += 128){
        int c = i >> 4, lq = i & 15;
        float4 v = *(const float4*)&x[(b*64 + c)*LL + l0 + lq*4];
        *(float4*)&xsm[c][lq*4] = v;
    }
    for (int i = tid; i < 1024; i += 128){
        int dl = i >> 4, c4 = i & 15;
        float4 v = *(const float4*)&Wp[(d0 + dl)*64 + c4*4];
        wsm[c4*4+0][dl] = v.x; wsm[c4*4+1][dl] = v.y;
        wsm[c4*4+2][dl] = v.z; wsm[c4*4+3][dl] = v.w;
    }
    __syncthreads();
    int tl = (tid & 15) << 2;
    int td = (tid >> 4) << 3;
    unsigned long long acc2[4][4];
#pragma unroll
    for (int i = 0; i < 4; i++)
#pragma unroll
        for (int j = 0; j < 4; j++) acc2[i][j] = 0ull;
#pragma unroll 8
    for (int k = 0; k < 64; k++){
        float4 a  = *(const float4*)&xsm[k][tl];
        float4 b0 = *(const float4*)&wsm[k][td];
        float4 b1 = *(const float4*)&wsm[k][td+4];
        unsigned long long bp0 = pk2(b0.x, b0.y), bp1 = pk2(b0.z, b0.w);
        unsigned long long bp2 = pk2(b1.x, b1.y), bp3 = pk2(b1.z, b1.w);
        float av[4] = {a.x, a.y, a.z, a.w};
#pragma unroll
        for (int i = 0; i < 4; i++){
            unsigned long long ap = pk2(av[i], av[i]);
            fma2(acc2[i][0], ap, bp0);
            fma2(acc2[i][1], ap, bp1);
            fma2(acc2[i][2], ap, bp2);
            fma2(acc2[i][3], ap, bp3);
        }
    }
    bool isz = (d0 >= 128);
    int dbase = d0 - (isz ? 128 : 0) + td;
    float* dst0 = isz ? g_zg : g_xin;
#pragma unroll
    for (int li = 0; li < 4; li++){
        float* dst = dst0 + (b*LL + l0 + tl + li)*DD + dbase;
        float2 p0 = up2(acc2[li][0]), p1 = up2(acc2[li][1]);
        float2 p2 = up2(acc2[li][2]), p3 = up2(acc2[li][3]);
        float4 o0, o1;
        if (isz){
            o0.x = gelu_exact(p0.x); o0.y = gelu_exact(p0.y);
            o0.z = gelu_exact(p1.x); o0.w = gelu_exact(p1.y);
            o1.x = gelu_exact(p2.x); o1.y = gelu_exact(p2.y);
            o1.z = gelu_exact(p3.x); o1.w = gelu_exact(p3.y);
        } else {
            o0 = make_float4(p0.x, p0.y, p1.x, p1.y);
            o1 = make_float4(p2.x, p2.y, p3.x, p3.y);
        }
        *(float4*)&dst[0] = o0;
        *(float4*)&dst[4] = o1;
    }
}

// ------------------------------------------------- K2: depthwise 3x3 conv + gelu
__global__ void k2_conv(const float* __restrict__ cw, const float* __restrict__ cb){
    __shared__ float swf[1152];
    __shared__ float sbf[128];
    int tid = threadIdx.x;
    for (int i = tid; i < 1152; i += 256) swf[i] = cw[i];
    if (tid < 128) sbf[tid] = cb[tid];
    __syncthreads();
    int idx = blockIdx.x*256 + tid;
    int d4 = idx & 31;
    int p  = idx >> 5;
    int w0 = (p & 31) << 2;
    int h  = (p >> 5) & 127;
    int b  = p >> 12;
    int d  = d4 << 2;
    float wr[3][3][4];
#pragma unroll
    for (int dd = 0; dd < 4; dd++)
#pragma unroll
        for (int kh = 0; kh < 3; kh++)
#pragma unroll
            for (int kw = 0; kw < 3; kw++)
                wr[kh][kw][dd] = swf[(d+dd)*9 + kh*3 + kw];
    float4 a[4];
#pragma unroll
    for (int i = 0; i < 4; i++)
        a[i] = make_float4(sbf[d], sbf[d+1], sbf[d+2], sbf[d+3]);
#pragma unroll
    for (int kh = 0; kh < 3; kh++){
        int hh = h + kh - 1;
        if (hh < 0 || hh > 127) continue;
        const float* base = &g_xin[(b*LL + hh*128)*DD + d];
        float4 r[6];
#pragma unroll
        for (int j = 0; j < 6; j++){
            int wj = w0 - 1 + j;
            r[j] = (wj >= 0 && wj < 128) ? *(const float4*)&base[wj*DD]
                                         : make_float4(0.f,0.f,0.f,0.f);
        }
#pragma unroll
        for (int kw = 0; kw < 3; kw++){
#pragma unroll
            for (int i = 0; i < 4; i++){
                float4 v = r[i+kw];
                a[i].x = fmaf(v.x, wr[kh][kw][0], a[i].x);
                a[i].y = fmaf(v.y, wr[kh][kw][1], a[i].y);
                a[i].z = fmaf(v.z, wr[kh][kw][2], a[i].z);
                a[i].w = fmaf(v.w, wr[kh][kw][3], a[i].w);
            }
        }
    }
#pragma unroll
    for (int i = 0; i < 4; i++){
        float4 o;
        o.x = gelu_exact(a[i].x); o.y = gelu_exact(a[i].y);
        o.z = gelu_exact(a[i].z); o.w = gelu_exact(a[i].w);
        *(float4*)&g_xs[(b*LL + h*128 + w0 + i)*DD + d] = o;
    }
}

// ---------------------------------------------------------------- K3: x_proj (v3)
// block 256, tile 64 l x 20 c; 2-way split accumulators to halve dep chains.
__global__ void __launch_bounds__(256) k3_xproj(const float* __restrict__ xw){
    __shared__ float xsm[64][132];
    __shared__ float wsm[20][132];
    int tid = threadIdx.x;
    int b  = blockIdx.x >> 8;
    int l0 = (blockIdx.x & 255) << 6;
    for (int i = tid; i < 2048; i += 256){
        int l = i >> 5, dq = i & 31;
        float4 v = *(const float4*)&g_xs[(b*LL + l0 + l)*DD + dq*4];
        *(float4*)&xsm[l][dq*4] = v;
    }
    for (int i = tid; i < 2560; i += 256)
        wsm[i >> 7][i & 127] = xw[i];
    __syncthreads();
    int lq = tid & 63;
    int c0 = (tid >> 6) * 5;
    float accA[5] = {0,0,0,0,0}, accB[5] = {0,0,0,0,0};
#pragma unroll 4
    for (int k8 = 0; k8 < 16; k8++){
        float4 xv0 = *(const float4*)&xsm[lq][k8*8];
        float4 xv1 = *(const float4*)&xsm[lq][k8*8+4];
#pragma unroll
        for (int j = 0; j < 5; j++){
            float4 w0 = *(const float4*)&wsm[c0+j][k8*8];
            float4 w1 = *(const float4*)&wsm[c0+j][k8*8+4];
            accA[j] = fmaf(xv0.w, w0.w, fmaf(xv0.z, w0.z, fmaf(xv0.y, w0.y, fmaf(xv0.x, w0.x, accA[j]))));
            accB[j] = fmaf(xv1.w, w1.w, fmaf(xv1.z, w1.z, fmaf(xv1.y, w1.y, fmaf(xv1.x, w1.x, accB[j]))));
        }
    }
#pragma unroll
    for (int j = 0; j < 5; j++)
        g_xdbl[(b*DBL + c0 + j)*LL + l0 + lq] = accA[j] + accB[j];
}

// ---- K45: 1D conv7 + dt_proj + softplus + scan phase 1, fused per (b, 64-l chunk)
__global__ void __launch_bounds__(128) k45_delta_scan1(
        const float* __restrict__ xcw, const float* __restrict__ xcb,
        const float* __restrict__ dpw, const float* __restrict__ dpb){
    __shared__ float xd[20][72];
    __shared__ float dtsm[4][64];
    __shared__ float bcs[64][17];
    int tid = threadIdx.x;
    int b  = blockIdx.x >> 8;
    int ch = blockIdx.x & 255;
    int l0 = ch << 6;
    for (int i = tid; i < 1400; i += 128){
        int c = i / 70, o = i % 70;
        int gl = l0 + o - 3;
        xd[c][o] = (gl >= 0 && gl < LL) ? g_xdbl[(b*DBL + c)*LL + gl] : 0.f;
    }
    __syncthreads();
    for (int i = tid; i < 1280; i += 128){
        int c = i >> 6, l = i & 63;
        float s = xcb[c];
#pragma unroll
        for (int j = 0; j < 7; j++) s = fmaf(xd[c][l + j], xcw[c*7+j], s);
        if (c < 4) dtsm[c][l] = s;
        else       bcs[l][c-4] = s;
    }
    __syncthreads();
    // write B/C for k78
    for (int i = tid; i < 512; i += 128){
        int l = i >> 3, n = i & 7;
        g_Bn[(b*LL + l0 + l)*NS + n] = bcs[l][n];
        g_Cn[(b*LL + l0 + l)*NS + n] = bcs[l][8+n];
    }
    // per-thread d: delta + scan phase 1
    float w0 = dpw[tid*4+0], w1 = dpw[tid*4+1], w2 = dpw[tid*4+2], w3 = dpw[tid*4+3];
    float bias = dpb[tid];
    float A[8];
#pragma unroll
    for (int n = 0; n < 8; n++) A[n] = g_Ascl[tid*8+n];
    int fast = g_afast;
    float h[8], ap[8];
#pragma unroll
    for (int n = 0; n < 8; n++){ h[n] = 0.f; ap[n] = 1.f; }
    int base = (b*LL + l0)*DD + tid;
    float u = g_xs[base];
    if (fast){
        for (int s = 0; s < CHL; s++){
            float un = (s < CHL-1) ? g_xs[base + (s+1)*DD] : 0.f;
            float sv = bias;
            sv = fmaf(dtsm[0][s], w0, sv);
            sv = fmaf(dtsm[1][s], w1, sv);
            sv = fmaf(dtsm[2][s], w2, sv);
            sv = fmaf(dtsm[3][s], w3, sv);
            float dl = softplus_fast(sv);
            g_delta[base + s*DD] = dl;
            float du = dl*u;
            float r = ex2(dl*A[0]);
            float dA = r;
#pragma unroll
            for (int n = 0; n < 8; n++){
                ap[n] *= dA;
                h[n] = fmaf(dA, h[n], du*bcs[s][n]);
                dA *= r;
            }
            u = un;
        }
    } else {
        for (int s = 0; s < CHL; s++){
            float un = (s < CHL-1) ? g_xs[base + (s+1)*DD] : 0.f;
            float sv = bias;
            sv = fmaf(dtsm[0][s], w0, sv);
            sv = fmaf(dtsm[1][s], w1, sv);
            sv = fmaf(dtsm[2][s], w2, sv);
            sv = fmaf(dtsm[3][s], w3, sv);
            float dl = softplus_fast(sv);
            g_delta[base + s*DD] = dl;
            float du = dl*u;
#pragma unroll
            for (int n = 0; n < 8; n++){
                float dA = ex2(dl*A[n]);
                ap[n] *= dA;
                h[n] = fmaf(dA, h[n], du*bcs[s][n]);
            }
            u = un;
        }
    }
    int o = ((b*NCH + ch)*DD + tid)*NS;
#pragma unroll
    for (int n = 0; n < 8; n++){ g_ap[o+n] = ap[n]; g_hs[o+n] = h[n]; }
}

// ------------------------------------------------ K6: scan phase 2 (over chunks)
__global__ void k6_scan2(){
    int idx = blockIdx.x*256 + threadIdx.x;  // 4096 = B*D*NS
    int b  = idx >> 10;
    int dn = idx & 1023;
    const float* ap = g_ap + b*NCH*1024 + dn;
    const float* hs = g_hs + b*NCH*1024 + dn;
    float*       hi = g_hi + b*NCH*1024 + dn;
    float h = 0.f;
#pragma unroll 8
    for (int ch = 0; ch < NCH; ch++){
        int o = ch << 10;
        float a = ap[o], s = hs[o];
        hi[o] = h;
        h = fmaf(a, h, s);
    }
}

// ---- K78: scan phase 3 (replay, y in smem) + LayerNorm*gate + out_proj + transpose
__global__ void __launch_bounds__(128) k78_scan3_out(
        const float* __restrict__ Dsv,
        const float* __restrict__ lg, const float* __restrict__ lb,
        const float* __restrict__ W2, float* __restrict__ out){
    __shared__ float Bs[CHL][NS];
    __shared__ float Cs[CHL][NS];
    __shared__ float ysm[64][136];  // col = d + (d>>6)*4 -> conflict-free fp4 reads
    __shared__ float vsm[64][68];   // [k_local][l]
    __shared__ float wsm[64][68];   // [k_local][c]
    int tid = threadIdx.x;
    int b  = blockIdx.x >> 8;
    int ch = blockIdx.x & 255;
    int l0 = ch << 6;
    for (int i = tid; i < CHL*NS; i += 128){
        ((float*)Bs)[i] = g_Bn[(b*LL + l0)*NS + i];
        ((float*)Cs)[i] = g_Cn[(b*LL + l0)*NS + i];
    }
    float A[8];
#pragma unroll
    for (int n = 0; n < 8; n++) A[n] = g_Ascl[tid*8+n];
    int fast = g_afast;
    float h[8];
    int o = ((b*NCH + ch)*DD + tid)*NS;
#pragma unroll
    for (int n = 0; n < 8; n++) h[n] = g_hi[o+n];
    float Dd = Dsv[tid];
    __syncthreads();
    int base = (b*LL + l0)*DD + tid;
    int ycol = tid + (tid >> 6)*4;
    float dl = g_delta[base], u = g_xs[base];
    if (fast){
#pragma unroll 2
        for (int s = 0; s < CHL; s++){
            float dn = 0.f, un = 0.f;
            if (s < CHL-1){ dn = g_delta[base + (s+1)*DD]; un = g_xs[base + (s+1)*DD]; }
            float du = dl*u;
            float y = Dd * u;
            float r = ex2(dl*A[0]);
            float dA = r;
#pragma unroll
            for (int n = 0; n < 8; n++){
                h[n] = fmaf(dA, h[n], du*Bs[s][n]);
                y = fmaf(h[n], Cs[s][n], y);
                dA *= r;
            }
            ysm[s][ycol] = y;
            dl = dn; u = un;
        }
    } else {
#pragma unroll 2
        for (int s = 0; s < CHL; s++){
            float dn = 0.f, un = 0.f;
            if (s < CHL-1){ dn = g_delta[base + (s+1)*DD]; un = g_xs[base + (s+1)*DD]; }
            float du = dl*u;
            float y = Dd * u;
#pragma unroll
            for (int n = 0; n < 8; n++){
                float dA = ex2(dl*A[n]);
                h[n] = fmaf(dA, h[n], du*Bs[s][n]);
                y = fmaf(h[n], Cs[s][n], y);
            }
            ysm[s][ycol] = y;
            dl = dn; u = un;
        }
    }
    __syncthreads();
    // ---- phase B: LN * gelu(z) gate + out_proj GEMM + transpose (k8 logic) ----
    int r = tid >> 1;        // row (l) 0..63
    int q = tid & 1;         // k-half owned by this thread
    const float* yrow = &ysm[r][q*68];   // 64 floats of this half
    const float* zrow = &g_zg[(b*LL + l0 + r)*DD + q*64];
    float s = 0.f, ss = 0.f;
#pragma unroll
    for (int i = 0; i < 16; i++){
        float4 v = *(const float4*)&yrow[i*4];
        s  += v.x + v.y + v.z + v.w;
        ss += v.x*v.x + v.y*v.y + v.z*v.z + v.w*v.w;
    }
    s  += __shfl_xor_sync(0xffffffffu, s, 1);
    ss += __shfl_xor_sync(0xffffffffu, ss, 1);
    float mu  = s * 0.0078125f;
    float var = fmaxf(ss * 0.0078125f - mu*mu, 0.f);
    float rstd = rsqrtf(var + 1e-5f);

    int tc = tid & 15;       // c group
    int tl = tid >> 4;       // l group
    unsigned long long acc2[8][2];
#pragma unroll
    for (int i = 0; i < 8; i++){ acc2[i][0] = 0ull; acc2[i][1] = 0ull; }

    for (int half = 0; half < 2; half++){
        __syncthreads();
        if (q == half){
#pragma unroll 4
            for (int i = 0; i < 16; i++){
                float4 yv = *(const float4*)&yrow[i*4];
                float4 zv = *(const float4*)&zrow[i*4];   // already gelu(z)
                float4 gv = *(const float4*)&lg[q*64 + i*4];
                float4 bv = *(const float4*)&lb[q*64 + i*4];
                vsm[i*4+0][r] = fmaf((yv.x-mu)*rstd, gv.x, bv.x) * zv.x;
                vsm[i*4+1][r] = fmaf((yv.y-mu)*rstd, gv.y, bv.y) * zv.y;
                vsm[i*4+2][r] = fmaf((yv.z-mu)*rstd, gv.z, bv.z) * zv.z;
                vsm[i*4+3][r] = fmaf((yv.w-mu)*rstd, gv.w, bv.w) * zv.w;
            }
        } else {
            for (int i = r; i < 1024; i += 64){
                int c = i >> 4, kq = i & 15;
                float4 wv = *(const float4*)&W2[c*DD + half*64 + kq*4];
                wsm[kq*4+0][c] = wv.x; wsm[kq*4+1][c] = wv.y;
                wsm[kq*4+2][c] = wv.z; wsm[kq*4+3][c] = wv.w;
            }
        }
        __syncthreads();
#pragma unroll 4
        for (int k = 0; k < 64; k++){
            float4 w  = *(const float4*)&wsm[k][tc*4];
            float4 v0 = *(const float4*)&vsm[k][tl*8];
            float4 v1 = *(const float4*)&vsm[k][tl*8+4];
            unsigned long long wp0 = pk2(w.x, w.y), wp1 = pk2(w.z, w.w);
            float vv[8] = {v0.x, v0.y, v0.z, v0.w, v1.x, v1.y, v1.z, v1.w};
#pragma unroll
            for (int i = 0; i < 8; i++){
                unsigned long long vp = pk2(vv[i], vv[i]);
                fma2(acc2[i][0], vp, wp0);
                fma2(acc2[i][1], vp, wp1);
            }
        }
    }
    __syncthreads();
#pragma unroll
    for (int i = 0; i < 8; i++){
        float2 p0 = up2(acc2[i][0]), p1 = up2(acc2[i][1]);
        vsm[tc*4+0][tl*8+i] = p0.x;
        vsm[tc*4+1][tl*8+i] = p0.y;
        vsm[tc*4+2][tl*8+i] = p1.x;
        vsm[tc*4+3][tl*8+i] = p1.y;
    }
    __syncthreads();
    for (int i = tid; i < 1024; i += 128){
        int c = i >> 4, lq = i & 15;
        float4 v = *(const float4*)&vsm[c][lq*4];
        *(float4*)&out[(b*64 + c)*LL + l0 + lq*4] = v;
    }
}

extern "C" void kernel_launch(void* const* d_in, const int* in_sizes, int n_in,
                              void* d_out, int out_size){
    const float* x          = (const float*)d_in[0];
    const float* in_proj_w  = (const float*)d_in[1];
    const float* conv2d_w   = (const float*)d_in[2];
    const float* conv2d_b   = (const float*)d_in[3];
    const float* x_proj_w   = (const float*)d_in[4];
    const float* x_conv_w   = (const float*)d_in[5];
    const float* x_conv_b   = (const float*)d_in[6];
    const float* dt_proj_w  = (const float*)d_in[7];
    const float* dt_proj_b  = (const float*)d_in[8];
    const float* A_logs     = (const float*)d_in[9];
    const float* Ds         = (const float*)d_in[10];
    const float* ln_g       = (const float*)d_in[11];
    const float* ln_b       = (const float*)d_in[12];
    const float* out_proj_w = (const float*)d_in[13];
    float* out = (float*)d_out;

    k0_prep        <<<   1, 128>>>(A_logs);
    k1_inproj      <<<4096, 128>>>(x, in_proj_w);
    k2_conv        <<<2048, 256>>>(conv2d_w, conv2d_b);
    k3_xproj       <<<1024, 256>>>(x_proj_w);
    k45_delta_scan1<<<1024, 128>>>(x_conv_w, x_conv_b, dt_proj_w, dt_proj_b);
    k6_scan2       <<<  16, 256>>>();
    k78_scan3_out  <<<1024, 128>>>(Ds, ln_g, ln_b, out_proj_w, out);
}

// round 8
// speedup vs baseline: 1.0401x; 1.0401x over previous
#include <cuda_runtime.h>
#include <math.h>

#define BB 4
#define CIN 64
#define LL 16384
#define DD 128
#define DBL 20
#define NS 8
#define NCH 256
#define CHL 64
#define LOG2E 1.4426950408889634f

__device__ float g_xin [BB*LL*DD];   // (b,l,d) pre-conv xin
__device__ float g_zg  [BB*LL*DD];   // gelu(z), (b,l,d)
__device__ float g_xs  [BB*LL*DD];   // gelu(conv(xin)), (b,l,d)
__device__ float g_xdbl[BB*DBL*LL];  // (b,c,l) pre-1dconv
__device__ float g_delta[BB*LL*DD];  // (b,l,d)
__device__ float g_Bn  [BB*LL*NS];   // (b,l,n)
__device__ float g_Cn  [BB*LL*NS];   // (b,l,n)
__device__ float g_ap  [BB*NCH*DD*NS];
__device__ float g_hs  [BB*NCH*DD*NS];
__device__ float g_hi  [BB*NCH*DD*NS];
__device__ float g_y   [BB*LL*DD];   // (b,l,d)
__device__ float g_Ascl[DD*NS];      // -exp(A_logs)*log2e
__device__ int   g_afast;            // 1 if A[d][n] == (n+1)*A[d][0]

__device__ __forceinline__ float gelu_exact(float x){
    return 0.5f*x*(1.f + erff(x*0.70710678118654752f));
}
__device__ __forceinline__ float ex2(float x){
    float r; asm("ex2.approx.f32 %0, %1;" : "=f"(r) : "f"(x)); return r;
}
__device__ __forceinline__ float softplus_fast(float x){
    float e = __expf(-fabsf(x));
    return fmaxf(x, 0.f) + __logf(1.f + e);
}
// packed fp32x2 helpers
__device__ __forceinline__ unsigned long long pk2(float a, float b){
    unsigned long long r; asm("mov.b64 %0, {%1, %2};" : "=l"(r) : "f"(a), "f"(b)); return r;
}
__device__ __forceinline__ void fma2(unsigned long long &d, unsigned long long a, unsigned long long b){
    asm("fma.rn.f32x2 %0, %1, %2, %0;" : "+l"(d) : "l"(a), "l"(b));
}
__device__ __forceinline__ float2 up2(unsigned long long v){
    float2 f; asm("mov.b64 {%0, %1}, %2;" : "=f"(f.x), "=f"(f.y) : "l"(v)); return f;
}

// ------------------------------------------- K0: precompute A scales + structure flag
__global__ void k0_prep(const float* __restrict__ A_logs){
    __shared__ int ok_sh;
    int tid = threadIdx.x;   // 128 = d
    if (tid == 0) ok_sh = 1;
    __syncthreads();
    float a[NS];
#pragma unroll
    for (int n = 0; n < NS; n++){
        a[n] = -__expf(A_logs[tid*NS+n]) * LOG2E;
        g_Ascl[tid*NS+n] = a[n];
    }
    bool ok = true;
#pragma unroll
    for (int n = 1; n < NS; n++)
        ok &= fabsf(a[n] - (n+1)*a[0]) <= 1e-5f * fabsf(a[n]);
    if (!ok) atomicAnd(&ok_sh, 0);
    __syncthreads();
    if (tid == 0) g_afast = ok_sh;
}

// ---------------------------------------------------------------- K1: in_proj
__global__ void k1_inproj(const float* __restrict__ x, const float* __restrict__ Wp){
    __shared__ float xsm[64][68];   // [c][l]
    __shared__ float wsm[64][68];   // [c][d_local]
    int tid = threadIdx.x;
    int lt = blockIdx.x >> 2;
    int dt = blockIdx.x & 3;
    int b  = lt >> 8;
    int l0 = (lt & 255) << 6;
    int d0 = dt << 6;
    for (int i = tid; i < 1024; i += 128){
        int c = i >> 4, lq = i & 15;
        float4 v = *(const float4*)&x[(b*64 + c)*LL + l0 + lq*4];
        *(float4*)&xsm[c][lq*4] = v;
    }
    for (int i = tid; i < 1024; i += 128){
        int dl = i >> 4, c4 = i & 15;
        float4 v = *(const float4*)&Wp[(d0 + dl)*64 + c4*4];
        wsm[c4*4+0][dl] = v.x; wsm[c4*4+1][dl] = v.y;
        wsm[c4*4+2][dl] = v.z; wsm[c4*4+3][dl] = v.w;
    }
    __syncthreads();
    int tl = (tid & 15) << 2;
    int td = (tid >> 4) << 3;
    unsigned long long acc2[4][4];
#pragma unroll
    for (int i = 0; i < 4; i++)
#pragma unroll
        for (int j = 0; j < 4; j++) acc2[i][j] = 0ull;
#pragma unroll 8
    for (int k = 0; k < 64; k++){
        float4 a  = *(const float4*)&xsm[k][tl];
        float4 b0 = *(const float4*)&wsm[k][td];
        float4 b1 = *(const float4*)&wsm[k][td+4];
        unsigned long long bp0 = pk2(b0.x, b0.y), bp1 = pk2(b0.z, b0.w);
        unsigned long long bp2 = pk2(b1.x, b1.y), bp3 = pk2(b1.z, b1.w);
        float av[4] = {a.x, a.y, a.z, a.w};
#pragma unroll
        for (int i = 0; i < 4; i++){
            unsigned long long ap = pk2(av[i], av[i]);
            fma2(acc2[i][0], ap, bp0);
            fma2(acc2[i][1], ap, bp1);
            fma2(acc2[i][2], ap, bp2);
            fma2(acc2[i][3], ap, bp3);
        }
    }
    bool isz = (d0 >= 128);
    int dbase = d0 - (isz ? 128 : 0) + td;
    float* dst0 = isz ? g_zg : g_xin;
#pragma unroll
    for (int li = 0; li < 4; li++){
        float* dst = dst0 + (b*LL + l0 + tl + li)*DD + dbase;
        float2 p0 = up2(acc2[li][0]), p1 = up2(acc2[li][1]);
        float2 p2 = up2(acc2[li][2]), p3 = up2(acc2[li][3]);
        float4 o0, o1;
        if (isz){
            o0.x = gelu_exact(p0.x); o0.y = gelu_exact(p0.y);
            o0.z = gelu_exact(p1.x); o0.w = gelu_exact(p1.y);
            o1.x = gelu_exact(p2.x); o1.y = gelu_exact(p2.y);
            o1.z = gelu_exact(p3.x); o1.w = gelu_exact(p3.y);
        } else {
            o0 = make_float4(p0.x, p0.y, p1.x, p1.y);
            o1 = make_float4(p2.x, p2.y, p3.x, p3.y);
        }
        *(float4*)&dst[0] = o0;
        *(float4*)&dst[4] = o1;
    }
}

// ------------------------------------------------- K2: depthwise 3x3 conv + gelu
__global__ void k2_conv(const float* __restrict__ cw, const float* __restrict__ cb){
    __shared__ float swf[1152];
    __shared__ float sbf[128];
    int tid = threadIdx.x;
    for (int i = tid; i < 1152; i += 256) swf[i] = cw[i];
    if (tid < 128) sbf[tid] = cb[tid];
    __syncthreads();
    int idx = blockIdx.x*256 + tid;
    int d4 = idx & 31;
    int p  = idx >> 5;
    int w0 = (p & 31) << 2;
    int h  = (p >> 5) & 127;
    int b  = p >> 12;
    int d  = d4 << 2;
    float wr[3][3][4];
#pragma unroll
    for (int dd = 0; dd < 4; dd++)
#pragma unroll
        for (int kh = 0; kh < 3; kh++)
#pragma unroll
            for (int kw = 0; kw < 3; kw++)
                wr[kh][kw][dd] = swf[(d+dd)*9 + kh*3 + kw];
    float4 a[4];
#pragma unroll
    for (int i = 0; i < 4; i++)
        a[i] = make_float4(sbf[d], sbf[d+1], sbf[d+2], sbf[d+3]);
#pragma unroll
    for (int kh = 0; kh < 3; kh++){
        int hh = h + kh - 1;
        if (hh < 0 || hh > 127) continue;
        const float* base = &g_xin[(b*LL + hh*128)*DD + d];
        float4 r[6];
#pragma unroll
        for (int j = 0; j < 6; j++){
            int wj = w0 - 1 + j;
            r[j] = (wj >= 0 && wj < 128) ? *(const float4*)&base[wj*DD]
                                         : make_float4(0.f,0.f,0.f,0.f);
        }
#pragma unroll
        for (int kw = 0; kw < 3; kw++){
#pragma unroll
            for (int i = 0; i < 4; i++){
                float4 v = r[i+kw];
                a[i].x = fmaf(v.x, wr[kh][kw][0], a[i].x);
                a[i].y = fmaf(v.y, wr[kh][kw][1], a[i].y);
                a[i].z = fmaf(v.z, wr[kh][kw][2], a[i].z);
                a[i].w = fmaf(v.w, wr[kh][kw][3], a[i].w);
            }
        }
    }
#pragma unroll
    for (int i = 0; i < 4; i++){
        float4 o;
        o.x = gelu_exact(a[i].x); o.y = gelu_exact(a[i].y);
        o.z = gelu_exact(a[i].z); o.w = gelu_exact(a[i].w);
        *(float4*)&g_xs[(b*LL + h*128 + w0 + i)*DD + d] = o;
    }
}

// ---------------------------------------------------------------- K3: x_proj (v4)
// K=128 reduction split into two K=64 phases over one small smem buffer:
// smem 23KB -> 8 blocks/SM (64 warps) instead of 4 (32 warps).
__global__ void __launch_bounds__(256) k3_xproj(const float* __restrict__ xw){
    __shared__ float xsm[64][68];   // [l][k_half]
    __shared__ float wsm[20][68];   // [c][k_half]
    int tid = threadIdx.x;
    int b  = blockIdx.x >> 8;
    int l0 = (blockIdx.x & 255) << 6;
    int lq = tid & 63;
    int c0 = (tid >> 6) * 5;
    float acc[5] = {0.f, 0.f, 0.f, 0.f, 0.f};
#pragma unroll
    for (int kk = 0; kk < 2; kk++){
        if (kk) __syncthreads();   // drain phase-0 readers before overwrite
        for (int i = tid; i < 1024; i += 256){     // 64 l * 16 float4
            int l = i >> 4, dq = i & 15;
            float4 v = *(const float4*)&g_xs[(b*LL + l0 + l)*DD + kk*64 + dq*4];
            *(float4*)&xsm[l][dq*4] = v;
        }
        for (int i = tid; i < 1280; i += 256){     // 20 c * 64 k
            int c = i >> 6, k = i & 63;
            wsm[c][k] = xw[c*DD + kk*64 + k];
        }
        __syncthreads();
#pragma unroll 4
        for (int k4 = 0; k4 < 16; k4++){
            float4 xv = *(const float4*)&xsm[lq][k4*4];
            float4 w0 = *(const float4*)&wsm[c0+0][k4*4];
            float4 w1 = *(const float4*)&wsm[c0+1][k4*4];
            float4 w2 = *(const float4*)&wsm[c0+2][k4*4];
            float4 w3 = *(const float4*)&wsm[c0+3][k4*4];
            float4 w4 = *(const float4*)&wsm[c0+4][k4*4];
            acc[0] = fmaf(xv.w, w0.w, fmaf(xv.z, w0.z, fmaf(xv.y, w0.y, fmaf(xv.x, w0.x, acc[0]))));
            acc[1] = fmaf(xv.w, w1.w, fmaf(xv.z, w1.z, fmaf(xv.y, w1.y, fmaf(xv.x, w1.x, acc[1]))));
            acc[2] = fmaf(xv.w, w2.w, fmaf(xv.z, w2.z, fmaf(xv.y, w2.y, fmaf(xv.x, w2.x, acc[2]))));
            acc[3] = fmaf(xv.w, w3.w, fmaf(xv.z, w3.z, fmaf(xv.y, w3.y, fmaf(xv.x, w3.x, acc[3]))));
            acc[4] = fmaf(xv.w, w4.w, fmaf(xv.z, w4.z, fmaf(xv.y, w4.y, fmaf(xv.x, w4.x, acc[4]))));
        }
    }
#pragma unroll
    for (int j = 0; j < 5; j++)
        g_xdbl[(b*DBL + c0 + j)*LL + l0 + lq] = acc[j];
}

// ------------------------ K4: depthwise 1D conv(7, pad 3) + dt_proj + softplus
// grid 1024 (64 l each), block 128.
__global__ void k4_conv1d_delta(const float* __restrict__ xcw, const float* __restrict__ xcb,
                                const float* __restrict__ dpw, const float* __restrict__ dpb){
    __shared__ float xd[20][72];
    __shared__ float dtsm[4][64];
    __shared__ float bcs[64][17];
    int tid = threadIdx.x;
    int b  = blockIdx.x >> 8;
    int l0 = (blockIdx.x & 255) << 6;
    for (int i = tid; i < 1400; i += 128){
        int c = i / 70, o = i % 70;
        int gl = l0 + o - 3;
        xd[c][o] = (gl >= 0 && gl < LL) ? g_xdbl[(b*DBL + c)*LL + gl] : 0.f;
    }
    __syncthreads();
    for (int i = tid; i < 1280; i += 128){
        int c = i >> 6, l = i & 63;
        float s = xcb[c];
#pragma unroll
        for (int j = 0; j < 7; j++) s = fmaf(xd[c][l + j], xcw[c*7+j], s);
        if (c < 4) dtsm[c][l] = s;
        else       bcs[l][c-4] = s;
    }
    __syncthreads();
    for (int i = tid; i < 512; i += 128){
        int l = i >> 3, n = i & 7;
        g_Bn[(b*LL + l0 + l)*NS + n] = bcs[l][n];
        g_Cn[(b*LL + l0 + l)*NS + n] = bcs[l][8+n];
    }
    float w0 = dpw[tid*4+0], w1 = dpw[tid*4+1], w2 = dpw[tid*4+2], w3 = dpw[tid*4+3];
    float bias = dpb[tid];
#pragma unroll 4
    for (int l = 0; l < 64; l++){
        float s = bias;
        s = fmaf(dtsm[0][l], w0, s);
        s = fmaf(dtsm[1][l], w1, s);
        s = fmaf(dtsm[2][l], w2, s);
        s = fmaf(dtsm[3][l], w3, s);
        g_delta[(b*LL + l0 + l)*DD + tid] = softplus_fast(s);
    }
}

// ------------------------------------------------ K5: scan phase 1 (chunk local)
__global__ void k5_scan1(){
    __shared__ float Bs[CHL][NS];
    int tid = threadIdx.x;
    int b  = blockIdx.x >> 8;
    int ch = blockIdx.x & 255;
    int l0 = ch << 6;
    for (int i = tid; i < CHL*NS; i += 128)
        ((float*)Bs)[i] = g_Bn[(b*LL + l0)*NS + i];
    float A[8];
#pragma unroll
    for (int n = 0; n < 8; n++) A[n] = g_Ascl[tid*8+n];
    int fast = g_afast;
    float h[8], ap[8];
#pragma unroll
    for (int n = 0; n < 8; n++){ h[n] = 0.f; ap[n] = 1.f; }
    __syncthreads();
    int base = (b*LL + l0)*DD + tid;
    float dl = g_delta[base], u = g_xs[base];
    if (fast){
#pragma unroll 2
        for (int s = 0; s < CHL; s++){
            float dn = 0.f, un = 0.f;
            if (s < CHL-1){ dn = g_delta[base + (s+1)*DD]; un = g_xs[base + (s+1)*DD]; }
            float du = dl*u;
            float r = ex2(dl*A[0]);
            float dA = r;
#pragma unroll
            for (int n = 0; n < 8; n++){
                ap[n] *= dA;
                h[n] = fmaf(dA, h[n], du*Bs[s][n]);
                dA *= r;
            }
            dl = dn; u = un;
        }
    } else {
#pragma unroll 2
        for (int s = 0; s < CHL; s++){
            float dn = 0.f, un = 0.f;
            if (s < CHL-1){ dn = g_delta[base + (s+1)*DD]; un = g_xs[base + (s+1)*DD]; }
            float du = dl*u;
#pragma unroll
            for (int n = 0; n < 8; n++){
                float dA = ex2(dl*A[n]);
                ap[n] *= dA;
                h[n] = fmaf(dA, h[n], du*Bs[s][n]);
            }
            dl = dn; u = un;
        }
    }
    int o = ((b*NCH + ch)*DD + tid)*NS;
#pragma unroll
    for (int n = 0; n < 8; n++){ g_ap[o+n] = ap[n]; g_hs[o+n] = h[n]; }
}

// ------------------------------------------------ K6: scan phase 2 (over chunks)
__global__ void k6_scan2(){
    int idx = blockIdx.x*256 + threadIdx.x;  // 4096 = B*D*NS
    int b  = idx >> 10;
    int dn = idx & 1023;
    const float* ap = g_ap + b*NCH*1024 + dn;
    const float* hs = g_hs + b*NCH*1024 + dn;
    float*       hi = g_hi + b*NCH*1024 + dn;
    float h = 0.f;
#pragma unroll 8
    for (int ch = 0; ch < NCH; ch++){
        int o = ch << 10;
        float a = ap[o], s = hs[o];
        hi[o] = h;
        h = fmaf(a, h, s);
    }
}

// ------------------------------------------- K7: scan phase 3 (replay + emit y)
__global__ void k7_scan3(const float* __restrict__ Dsv){
    __shared__ float Bs[CHL][NS];
    __shared__ float Cs[CHL][NS];
    int tid = threadIdx.x;
    int b  = blockIdx.x >> 8;
    int ch = blockIdx.x & 255;
    int l0 = ch << 6;
    for (int i = tid; i < CHL*NS; i += 128){
        ((float*)Bs)[i] = g_Bn[(b*LL + l0)*NS + i];
        ((float*)Cs)[i] = g_Cn[(b*LL + l0)*NS + i];
    }
    float A[8];
#pragma unroll
    for (int n = 0; n < 8; n++) A[n] = g_Ascl[tid*8+n];
    int fast = g_afast;
    float h[8];
    int o = ((b*NCH + ch)*DD + tid)*NS;
#pragma unroll
    for (int n = 0; n < 8; n++) h[n] = g_hi[o+n];
    float Dd = Dsv[tid];
    __syncthreads();
    int base = (b*LL + l0)*DD + tid;
    float dl = g_delta[base], u = g_xs[base];
    if (fast){
#pragma unroll 2
        for (int s = 0; s < CHL; s++){
            float dn = 0.f, un = 0.f;
            if (s < CHL-1){ dn = g_delta[base + (s+1)*DD]; un = g_xs[base + (s+1)*DD]; }
            float du = dl*u;
            float y = Dd * u;
            float r = ex2(dl*A[0]);
            float dA = r;
#pragma unroll
            for (int n = 0; n < 8; n++){
                h[n] = fmaf(dA, h[n], du*Bs[s][n]);
                y = fmaf(h[n], Cs[s][n], y);
                dA *= r;
            }
            g_y[base + s*DD] = y;
            dl = dn; u = un;
        }
    } else {
#pragma unroll 2
        for (int s = 0; s < CHL; s++){
            float dn = 0.f, un = 0.f;
            if (s < CHL-1){ dn = g_delta[base + (s+1)*DD]; un = g_xs[base + (s+1)*DD]; }
            float du = dl*u;
            float y = Dd * u;
#pragma unroll
            for (int n = 0; n < 8; n++){
                float dA = ex2(dl*A[n]);
                h[n] = fmaf(dA, h[n], du*Bs[s][n]);
                y = fmaf(h[n], Cs[s][n], y);
            }
            g_y[base + s*DD] = y;
            dl = dn; u = un;
        }
    }
}

// --------------- K8: fused LayerNorm * gate + out_proj GEMM + transpose
__global__ void k8_fused(const float* __restrict__ lg, const float* __restrict__ lb,
                         const float* __restrict__ W2, float* __restrict__ out){
    __shared__ float vsm[64][68];   // [k_local][l]
    __shared__ float wsm[64][68];   // [k_local][c]
    int tid = threadIdx.x;
    int b  = blockIdx.x >> 8;
    int l0 = (blockIdx.x & 255) << 6;
    int r = tid >> 1;        // row (l) 0..63
    int q = tid & 1;         // k-half owned by this thread
    const float* yrow = &g_y[(b*LL + l0 + r)*DD + q*64];
    const float* zrow = &g_zg[(b*LL + l0 + r)*DD + q*64];
    float s = 0.f, ss = 0.f;
#pragma unroll
    for (int i = 0; i < 16; i++){
        float4 v = *(const float4*)&yrow[i*4];
        s  += v.x + v.y + v.z + v.w;
        ss += v.x*v.x + v.y*v.y + v.z*v.z + v.w*v.w;
    }
    s  += __shfl_xor_sync(0xffffffffu, s, 1);
    ss += __shfl_xor_sync(0xffffffffu, ss, 1);
    float mu  = s * 0.0078125f;
    float var = fmaxf(ss * 0.0078125f - mu*mu, 0.f);
    float rstd = rsqrtf(var + 1e-5f);

    int tc = tid & 15;       // c group: c = tc*4
    int tl = tid >> 4;       // l group: l = tl*8
    unsigned long long acc2[8][2];
#pragma unroll
    for (int i = 0; i < 8; i++){ acc2[i][0] = 0ull; acc2[i][1] = 0ull; }

    for (int half = 0; half < 2; half++){
        __syncthreads();
        if (q == half){
#pragma unroll 4
            for (int i = 0; i < 16; i++){
                float4 yv = *(const float4*)&yrow[i*4];
                float4 zv = *(const float4*)&zrow[i*4];   // already gelu(z)
                float4 gv = *(const float4*)&lg[q*64 + i*4];
                float4 bv = *(const float4*)&lb[q*64 + i*4];
                vsm[i*4+0][r] = fmaf((yv.x-mu)*rstd, gv.x, bv.x) * zv.x;
                vsm[i*4+1][r] = fmaf((yv.y-mu)*rstd, gv.y, bv.y) * zv.y;
                vsm[i*4+2][r] = fmaf((yv.z-mu)*rstd, gv.z, bv.z) * zv.z;
                vsm[i*4+3][r] = fmaf((yv.w-mu)*rstd, gv.w, bv.w) * zv.w;
            }
        } else {
            for (int i = r; i < 1024; i += 64){
                int c = i >> 4, kq = i & 15;
                float4 wv = *(const float4*)&W2[c*DD + half*64 + kq*4];
                wsm[kq*4+0][c] = wv.x; wsm[kq*4+1][c] = wv.y;
                wsm[kq*4+2][c] = wv.z; wsm[kq*4+3][c] = wv.w;
            }
        }
        __syncthreads();
#pragma unroll 4
        for (int k = 0; k < 64; k++){
            float4 w  = *(const float4*)&wsm[k][tc*4];
            float4 v0 = *(const float4*)&vsm[k][tl*8];
            float4 v1 = *(const float4*)&vsm[k][tl*8+4];
            unsigned long long wp0 = pk2(w.x, w.y), wp1 = pk2(w.z, w.w);
            float vv[8] = {v0.x, v0.y, v0.z, v0.w, v1.x, v1.y, v1.z, v1.w};
#pragma unroll
            for (int i = 0; i < 8; i++){
                unsigned long long vp = pk2(vv[i], vv[i]);
                fma2(acc2[i][0], vp, wp0);
                fma2(acc2[i][1], vp, wp1);
            }
        }
    }
    __syncthreads();
#pragma unroll
    for (int i = 0; i < 8; i++){
        float2 p0 = up2(acc2[i][0]), p1 = up2(acc2[i][1]);
        vsm[tc*4+0][tl*8+i] = p0.x;
        vsm[tc*4+1][tl*8+i] = p0.y;
        vsm[tc*4+2][tl*8+i] = p1.x;
        vsm[tc*4+3][tl*8+i] = p1.y;
    }
    __syncthreads();
    for (int i = tid; i < 1024; i += 128){
        int c = i >> 4, lq = i & 15;
        float4 v = *(const float4*)&vsm[c][lq*4];
        *(float4*)&out[(b*64 + c)*LL + l0 + lq*4] = v;
    }
}

extern "C" void kernel_launch(void* const* d_in, const int* in_sizes, int n_in,
                              void* d_out, int out_size){
    const float* x          = (const float*)d_in[0];
    const float* in_proj_w  = (const float*)d_in[1];
    const float* conv2d_w   = (const float*)d_in[2];
    const float* conv2d_b   = (const float*)d_in[3];
    const float* x_proj_w   = (const float*)d_in[4];
    const float* x_conv_w   = (const float*)d_in[5];
    const float* x_conv_b   = (const float*)d_in[6];
    const float* dt_proj_w  = (const float*)d_in[7];
    const float* dt_proj_b  = (const float*)d_in[8];
    const float* A_logs     = (const float*)d_in[9];
    const float* Ds         = (const float*)d_in[10];
    const float* ln_g       = (const float*)d_in[11];
    const float* ln_b       = (const float*)d_in[12];
    const float* out_proj_w = (const float*)d_in[13];
    float* out = (float*)d_out;

    k0_prep        <<<   1, 128>>>(A_logs);
    k1_inproj      <<<4096, 128>>>(x, in_proj_w);
    k2_conv        <<<2048, 256>>>(conv2d_w, conv2d_b);
    k3_xproj       <<<1024, 256>>>(x_proj_w);
    k4_conv1d_delta<<<1024, 128>>>(x_conv_w, x_conv_b, dt_proj_w, dt_proj_b);
    k5_scan1       <<<1024, 128>>>();
    k6_scan2       <<<  16, 256>>>();
    k7_scan3       <<<1024, 128>>>(Ds);
    k8_fused       <<<1024, 128>>>(ln_g, ln_b, out_proj_w, out);
}